// round 2
// baseline (speedup 1.0000x reference)
#include <cuda_runtime.h>
#include <math.h>

#define NN 20000
#define KK 63
#define DD 50
#define EE 300

// scratch (allocation-free rule: __device__ globals)
__device__ float g_ent[NN * DD];
__device__ float g_node[NN * DD];

// ---------------------------------------------------------------------------
// Kernel 1: ent = entity_emb @ Wp.T + bp     [N,300] x [300,50] -> [N,50]
// 64-node tile, 16x16 threads, 4x4 register tile, chunked K=50, float4 smem.
// ---------------------------------------------------------------------------
__global__ __launch_bounds__(256) void ent_kernel(
    const float* __restrict__ eemb, const float* __restrict__ Wp,
    const float* __restrict__ bp)
{
    __shared__ float e_s[64][52];
    __shared__ float w_s[50][52];
    const int tx = threadIdx.x, ty = threadIdx.y;
    const int tid = ty * 16 + tx;
    const int n0 = blockIdx.x * 64;

    int  oc[4];
    bool ov[4];
#pragma unroll
    for (int cc = 0; cc < 4; cc++) {
        int o = cc * 13 + tx;
        ov[cc] = (tx < 13) && (o < DD);
        oc[cc] = ov[cc] ? o : 0;
    }

    float acc[4][4] = {};

    for (int cb = 0; cb < EE; cb += 50) {
        __syncthreads();
        for (int idx = tid; idx < 64 * 52; idx += 256) {
            int r = idx / 52, c = idx - r * 52;
            int n = n0 + r;
            e_s[r][c] = (c < 50 && n < NN) ? eemb[(size_t)n * EE + cb + c] : 0.f;
        }
        for (int idx = tid; idx < 50 * 52; idx += 256) {
            int r = idx / 52, c = idx - r * 52;
            w_s[r][c] = (c < 50) ? Wp[r * EE + cb + c] : 0.f;
        }
        __syncthreads();
#pragma unroll
        for (int j = 0; j < 52; j += 4) {
            float4 ev[4], bv[4];
#pragma unroll
            for (int rr = 0; rr < 4; rr++) ev[rr] = *(const float4*)&e_s[ty * 4 + rr][j];
#pragma unroll
            for (int cc = 0; cc < 4; cc++) bv[cc] = *(const float4*)&w_s[oc[cc]][j];
#pragma unroll
            for (int rr = 0; rr < 4; rr++)
#pragma unroll
                for (int cc = 0; cc < 4; cc++)
                    acc[rr][cc] += ev[rr].x * bv[cc].x + ev[rr].y * bv[cc].y
                                 + ev[rr].z * bv[cc].z + ev[rr].w * bv[cc].w;
        }
    }

#pragma unroll
    for (int rr = 0; rr < 4; rr++) {
        int n = n0 + ty * 4 + rr;
        if (n < NN) {
#pragma unroll
            for (int cc = 0; cc < 4; cc++)
                if (ov[cc]) g_ent[(size_t)n * DD + oc[cc]] = acc[rr][cc] + bp[oc[cc]];
        }
    }
}

// ---------------------------------------------------------------------------
// Kernel 2: node[n,o] = sum_{i,j} q[n,i] Wbil[o,i,j] ent[n,j] + bbil[o]
// GEMM [N,2500]x[2500,50] with the [N,2500] operand (q outer ent) formed on
// the fly. Per i-slice: tmp[n,o] = ent[n,:] . Wbil[o,i,:];  acc += q[n,i]*tmp.
// ---------------------------------------------------------------------------
__global__ __launch_bounds__(256) void bil_kernel(
    const float* __restrict__ q, const float* __restrict__ Wbil,
    const float* __restrict__ bbil)
{
    __shared__ float q_s[64][52];
    __shared__ float ent_s[64][52];
    __shared__ float B_s[50][52];
    const int tx = threadIdx.x, ty = threadIdx.y;
    const int tid = ty * 16 + tx;
    const int n0 = blockIdx.x * 64;

    for (int idx = tid; idx < 64 * 52; idx += 256) {
        int r = idx / 52, c = idx - r * 52;
        int n = n0 + r;
        float qv = 0.f, ev = 0.f;
        if (c < 50 && n < NN) {
            qv = q[(size_t)n * DD + c];
            ev = g_ent[(size_t)n * DD + c];
        }
        q_s[r][c] = qv;
        ent_s[r][c] = ev;
    }
    if (tid < 50) { B_s[tid][50] = 0.f; B_s[tid][51] = 0.f; }

    int  oc[4];
    bool ov[4];
#pragma unroll
    for (int cc = 0; cc < 4; cc++) {
        int o = cc * 13 + tx;
        ov[cc] = (tx < 13) && (o < DD);
        oc[cc] = ov[cc] ? o : 0;
    }

    float acc[4][4] = {};

    for (int i = 0; i < DD; i++) {
        __syncthreads();
        for (int idx = tid; idx < 2500; idx += 256) {
            int o = idx / 50, j = idx - o * 50;
            B_s[o][j] = Wbil[o * 2500 + i * 50 + j];
        }
        __syncthreads();

        float tmp[4][4] = {};
#pragma unroll
        for (int j = 0; j < 52; j += 4) {
            float4 ev[4], bv[4];
#pragma unroll
            for (int rr = 0; rr < 4; rr++) ev[rr] = *(const float4*)&ent_s[ty * 4 + rr][j];
#pragma unroll
            for (int cc = 0; cc < 4; cc++) bv[cc] = *(const float4*)&B_s[oc[cc]][j];
#pragma unroll
            for (int rr = 0; rr < 4; rr++)
#pragma unroll
                for (int cc = 0; cc < 4; cc++)
                    tmp[rr][cc] += ev[rr].x * bv[cc].x + ev[rr].y * bv[cc].y
                                 + ev[rr].z * bv[cc].z + ev[rr].w * bv[cc].w;
        }
#pragma unroll
        for (int rr = 0; rr < 4; rr++) {
            float qv = q_s[ty * 4 + rr][i];
#pragma unroll
            for (int cc = 0; cc < 4; cc++) acc[rr][cc] += qv * tmp[rr][cc];
        }
    }

#pragma unroll
    for (int rr = 0; rr < 4; rr++) {
        int n = n0 + ty * 4 + rr;
        if (n < NN) {
#pragma unroll
            for (int cc = 0; cc < 4; cc++)
                if (ov[cc]) g_node[(size_t)n * DD + oc[cc]] = acc[rr][cc] + bbil[oc[cc]];
        }
    }
}

// ---------------------------------------------------------------------------
// Kernel 3 (fused GRN + head), 4 nodes/block, 256 threads:
//   t[n,:]  = sum_{k<63} s[n,k]*nb[n,k,:] + s[n,63]*node[n,:]   (HBM-bound)
//   agg     = Wg @ t + g_bias ;  feats = elu(agg)
//   out[n]  = feats . Wr + br
// ---------------------------------------------------------------------------
__global__ __launch_bounds__(256) void grn_kernel(
    const float* __restrict__ nb, const float* __restrict__ sc,
    const float* __restrict__ Wg, const float* __restrict__ gb,
    const float* __restrict__ Wr, const float* __restrict__ br,
    float* __restrict__ out)
{
    __shared__ float Wg_s[2500];
    __shared__ float t_s[4][64];
    __shared__ float s_s[4][64];
    __shared__ float p_s[4][64];
    const int tid = threadIdx.x;
    const int n0 = blockIdx.x * 4;

    for (int idx = tid; idx < 2500; idx += 256) Wg_s[idx] = Wg[idx];
    {
        int v = tid >> 6, k = tid & 63;
        int n = n0 + v;
        s_s[v][k] = (n < NN) ? sc[(size_t)n * (KK + 1) + k] : 0.f;
    }
    __syncthreads();

    // weighted neighbor sum
    {
        int v = tid >> 6, d = tid & 63;
        int n = n0 + v;
        float acc = 0.f;
        if (n < NN && d < DD) {
            const float* base = nb + (size_t)n * (KK * DD) + d;
#pragma unroll 9
            for (int k = 0; k < KK; k++) acc += s_s[v][k] * base[k * DD];
            acc += s_s[v][KK] * g_node[(size_t)n * DD + d];
        }
        t_s[v][d] = acc;
    }
    __syncthreads();

    // agg = Wg @ t + g_bias ; elu ; scale by Wr
    {
        int v = tid >> 6, o = tid & 63;
        float r = 0.f;
        if (o < DD) {
            float a = gb[o];
            const float* wrow = Wg_s + o * DD;
#pragma unroll
            for (int dd = 0; dd < DD; dd++) a += wrow[dd] * t_s[v][dd];
            float f = (a > 0.f) ? a : expm1f(a);
            r = f * Wr[o];
        }
        p_s[v][o] = r;
    }
    __syncthreads();

    if (tid < 4) {
        int n = n0 + tid;
        if (n < NN) {
            float sum = 0.f;
#pragma unroll
            for (int o = 0; o < 64; o++) sum += p_s[tid][o];
            out[n] = sum + br[0];
        }
    }
}

// ---------------------------------------------------------------------------
extern "C" void kernel_launch(void* const* d_in, const int* in_sizes, int n_in,
                              void* d_out, int out_size)
{
    const float* q    = (const float*)d_in[0];
    const float* ee   = (const float*)d_in[1];
    const float* nb   = (const float*)d_in[2];
    const float* sc   = (const float*)d_in[3];
    const float* Wp   = (const float*)d_in[4];
    const float* bp   = (const float*)d_in[5];
    const float* Wbil = (const float*)d_in[6];
    const float* bbil = (const float*)d_in[7];
    const float* Wg   = (const float*)d_in[8];
    const float* gb   = (const float*)d_in[9];
    const float* Wr   = (const float*)d_in[10];
    const float* br   = (const float*)d_in[11];
    float* out = (float*)d_out;

    dim3 blk(16, 16);
    const int nb64 = (NN + 63) / 64;
    ent_kernel<<<nb64, blk>>>(ee, Wp, bp);
    bil_kernel<<<nb64, blk>>>(q, Wbil, bbil);
    grn_kernel<<<(NN + 3) / 4, 256>>>(nb, sc, Wg, gb, Wr, br, out);
}

// round 6
// speedup vs baseline: 1.1873x; 1.1873x over previous
#include <cuda_runtime.h>
#include <cuda_bf16.h>
#include <math.h>
#include <stdint.h>

#define NN 20000
#define KK 63
#define DD 50
#define EE 300

// scratch (allocation-free rule: __device__ globals)
__device__ float g_ent[NN * DD];
__device__ float g_node[NN * DD];
// Wbil pre-split bf16 hi/lo in mma.sync fragment order:
// index ((i*2 + wc)*16 + s*4 + a)*32 + lane  -> uint2 {b0,b1},{b2,b3}
__device__ uint2 g_Bh[50 * 2 * 16 * 32];
__device__ uint2 g_Bl[50 * 2 * 16 * 32];

// ---------------------------------------------------------------------------
// mma.sync m16n8k16 row.col f32.bf16.bf16.f32 (sm_80-era PTX; compute_103-safe)
// ---------------------------------------------------------------------------
__device__ __forceinline__ void mma16816(float d[4], const uint32_t a[4],
                                         const uint2 b, const float c[4]) {
    asm volatile(
        "mma.sync.aligned.m16n8k16.row.col.f32.bf16.bf16.f32 "
        "{%0,%1,%2,%3}, {%4,%5,%6,%7}, {%8,%9}, {%10,%11,%12,%13};"
        : "=f"(d[0]), "=f"(d[1]), "=f"(d[2]), "=f"(d[3])
        : "r"(a[0]), "r"(a[1]), "r"(a[2]), "r"(a[3]),
          "r"(b.x), "r"(b.y),
          "f"(c[0]), "f"(c[1]), "f"(c[2]), "f"(c[3]));
}

__device__ __forceinline__ uint32_t pack_bf16x2(float lo, float hi) {
    __nv_bfloat162 h = __float22bfloat162_rn(make_float2(lo, hi));
    return *(uint32_t*)&h;
}

// ---------------------------------------------------------------------------
// Prep: split Wbil into bf16 hi/lo and lay out in B-fragment order.
// For (i, wc, s, a, lane): o = wc*32 + a*8 + (lane>>2), j0 = s*16 + 2*(lane&3)
// elements: (j0, j0+1) -> .x,  (j0+8, j0+9) -> .y   (b0..b3 of m16n8k16 B frag)
// ---------------------------------------------------------------------------
__global__ void prep_kernel(const float* __restrict__ Wbil) {
    int idx = blockIdx.x * 256 + threadIdx.x;
    if (idx >= 50 * 2 * 16 * 32) return;
    int lane = idx & 31;
    int frag = (idx >> 5) & 15;
    int wc   = (idx >> 9) & 1;
    int i    = idx >> 10;
    int s = frag >> 2, a = frag & 3;
    int g = lane >> 2, t = lane & 3;
    int o = wc * 32 + a * 8 + g;
    int j0 = s * 16 + 2 * t;

    float v[4];
    int js[4] = { j0, j0 + 1, j0 + 8, j0 + 9 };
#pragma unroll
    for (int e = 0; e < 4; e++) {
        int j = js[e];
        v[e] = (o < DD && j < DD) ? Wbil[o * 2500 + i * 50 + j] : 0.f;
    }
    uint2 hi, lo;
    {
        __nv_bfloat162 h = __float22bfloat162_rn(make_float2(v[0], v[1]));
        float l0 = v[0] - __bfloat162float(h.x);
        float l1 = v[1] - __bfloat162float(h.y);
        hi.x = *(uint32_t*)&h;
        lo.x = pack_bf16x2(l0, l1);
    }
    {
        __nv_bfloat162 h = __float22bfloat162_rn(make_float2(v[2], v[3]));
        float l0 = v[2] - __bfloat162float(h.x);
        float l1 = v[3] - __bfloat162float(h.y);
        hi.y = *(uint32_t*)&h;
        lo.y = pack_bf16x2(l0, l1);
    }
    g_Bh[idx] = hi;
    g_Bl[idx] = lo;
}

// ---------------------------------------------------------------------------
// Kernel 1: ent = entity_emb @ Wp.T + bp  (fp32 tiled GEMM, unchanged)
// ---------------------------------------------------------------------------
__global__ __launch_bounds__(256) void ent_kernel(
    const float* __restrict__ eemb, const float* __restrict__ Wp,
    const float* __restrict__ bp)
{
    __shared__ float e_s[64][52];
    __shared__ float w_s[50][52];
    const int tx = threadIdx.x, ty = threadIdx.y;
    const int tid = ty * 16 + tx;
    const int n0 = blockIdx.x * 64;

    int  oc[4];
    bool ov[4];
#pragma unroll
    for (int cc = 0; cc < 4; cc++) {
        int o = cc * 13 + tx;
        ov[cc] = (tx < 13) && (o < DD);
        oc[cc] = ov[cc] ? o : 0;
    }
    float acc[4][4] = {};
    for (int cb = 0; cb < EE; cb += 50) {
        __syncthreads();
        for (int idx = tid; idx < 64 * 52; idx += 256) {
            int r = idx / 52, c = idx - r * 52;
            int n = n0 + r;
            e_s[r][c] = (c < 50 && n < NN) ? eemb[(size_t)n * EE + cb + c] : 0.f;
        }
        for (int idx = tid; idx < 50 * 52; idx += 256) {
            int r = idx / 52, c = idx - r * 52;
            w_s[r][c] = (c < 50) ? Wp[r * EE + cb + c] : 0.f;
        }
        __syncthreads();
#pragma unroll
        for (int j = 0; j < 52; j += 4) {
            float4 ev[4], bv[4];
#pragma unroll
            for (int rr = 0; rr < 4; rr++) ev[rr] = *(const float4*)&e_s[ty * 4 + rr][j];
#pragma unroll
            for (int cc = 0; cc < 4; cc++) bv[cc] = *(const float4*)&w_s[oc[cc]][j];
#pragma unroll
            for (int rr = 0; rr < 4; rr++)
#pragma unroll
                for (int cc = 0; cc < 4; cc++)
                    acc[rr][cc] += ev[rr].x * bv[cc].x + ev[rr].y * bv[cc].y
                                 + ev[rr].z * bv[cc].z + ev[rr].w * bv[cc].w;
        }
    }
#pragma unroll
    for (int rr = 0; rr < 4; rr++) {
        int n = n0 + ty * 4 + rr;
        if (n < NN) {
#pragma unroll
            for (int cc = 0; cc < 4; cc++)
                if (ov[cc]) g_ent[(size_t)n * DD + oc[cc]] = acc[rr][cc] + bp[oc[cc]];
        }
    }
}

// ---------------------------------------------------------------------------
// Kernel 2 (HMMA): node[n,o] = sum_i q[n,i] * (ent @ Wbil[:,i,:].T)[n,o] + bbil
// 128 nodes/CTA, 8 warps in 4(m) x 2(n) grid; warp tile 32(m) x 32(n).
// ent split hi/lo into A fragments ONCE; per i: 3 split-MMAs into D regs,
// then acc += q[n,i]*D in fp32. B frags coalesced from L2 (fragment order).
// ---------------------------------------------------------------------------
extern "C" __global__ void __launch_bounds__(256, 1)
bil_mma_kernel(const float* __restrict__ q, const float* __restrict__ bbil)
{
    __shared__ float sm[128 * 64];       // phase 1: ent[128][64]; phase 2: q_t[50][128]
    __shared__ float bbil_s[64];

    const int tid = threadIdx.x;
    const int lane = tid & 31, wid = tid >> 5;
    const int n0 = blockIdx.x * 128;
    const int g = lane >> 2, t = lane & 3;
    const int mo = (wid >> 1) * 32;      // warp m offset
    const int wc = wid & 1;              // warp n column (0/1)

    // ---- phase 1: stage ent (padded to 64 cols with zeros) ----
    for (int idx = tid; idx < 128 * 50; idx += 256) {
        int r = idx / 50, c = idx - r * 50;
        int n = n0 + r;
        sm[r * 64 + c] = (n < NN) ? g_ent[(size_t)n * DD + c] : 0.f;
    }
    for (int idx = tid; idx < 128 * 14; idx += 256) {
        int r = idx / 14, c = idx - r * 14;
        sm[r * 64 + 50 + c] = 0.f;
    }
    if (tid < 64) bbil_s[tid] = (tid < DD) ? bbil[tid] : 0.f;
    __syncthreads();

    // gather loop-invariant A fragments (hi/lo split once)
    uint32_t eh[2][4][4], el[2][4][4];
#pragma unroll
    for (int am = 0; am < 2; am++) {
#pragma unroll
        for (int s = 0; s < 4; s++) {
            int r0 = mo + 16 * am + g, r1 = r0 + 8;
            int c0 = 16 * s + 2 * t;
            float a0 = sm[r0 * 64 + c0],     a1 = sm[r0 * 64 + c0 + 1];
            float a2 = sm[r1 * 64 + c0],     a3 = sm[r1 * 64 + c0 + 1];
            float a4 = sm[r0 * 64 + c0 + 8], a5 = sm[r0 * 64 + c0 + 9];
            float a6 = sm[r1 * 64 + c0 + 8], a7 = sm[r1 * 64 + c0 + 9];
            float v[8] = { a0, a1, a2, a3, a4, a5, a6, a7 };
#pragma unroll
            for (int p = 0; p < 4; p++) {
                __nv_bfloat162 h = __float22bfloat162_rn(make_float2(v[2 * p], v[2 * p + 1]));
                float l0 = v[2 * p]     - __bfloat162float(h.x);
                float l1 = v[2 * p + 1] - __bfloat162float(h.y);
                eh[am][s][p] = *(uint32_t*)&h;
                el[am][s][p] = pack_bf16x2(l0, l1);
            }
        }
    }
    __syncthreads();

    // ---- phase 2: reuse smem for q transposed [50][128] ----
    for (int idx = tid; idx < 128 * 50; idx += 256) {
        int r = idx / 50, c = idx - r * 50;
        int n = n0 + r;
        sm[c * 128 + r] = (n < NN) ? q[(size_t)n * DD + c] : 0.f;
    }
    __syncthreads();

    float acc[2][4][4] = {};

    for (int i = 0; i < 50; i++) {
        const float* qrow = sm + i * 128 + mo;
        float qv[4] = { qrow[g], qrow[g + 8], qrow[g + 16], qrow[g + 24] };

        float d[2][4][4];
#pragma unroll
        for (int am = 0; am < 2; am++)
#pragma unroll
            for (int a = 0; a < 4; a++)
#pragma unroll
                for (int e = 0; e < 4; e++) d[am][a][e] = 0.f;

        const int base = ((i * 2 + wc) * 16) * 32 + lane;
#pragma unroll
        for (int s = 0; s < 4; s++) {
            uint2 bh[4], bl[4];
#pragma unroll
            for (int a = 0; a < 4; a++) {
                bh[a] = g_Bh[base + (s * 4 + a) * 32];
                bl[a] = g_Bl[base + (s * 4 + a) * 32];
            }
#pragma unroll
            for (int a = 0; a < 4; a++) {
#pragma unroll
                for (int am = 0; am < 2; am++) {
                    mma16816(d[am][a], eh[am][s], bh[a], d[am][a]);
                    mma16816(d[am][a], el[am][s], bh[a], d[am][a]);
                    mma16816(d[am][a], eh[am][s], bl[a], d[am][a]);
                }
            }
        }
#pragma unroll
        for (int am = 0; am < 2; am++) {
            float q0 = qv[2 * am], q1 = qv[2 * am + 1];
#pragma unroll
            for (int a = 0; a < 4; a++) {
                acc[am][a][0] += q0 * d[am][a][0];
                acc[am][a][1] += q0 * d[am][a][1];
                acc[am][a][2] += q1 * d[am][a][2];
                acc[am][a][3] += q1 * d[am][a][3];
            }
        }
    }

    // epilogue: C[g][2t] mapping -> rows n0+mo+16am+g(+8), cols wc*32+8a+2t(+1)
#pragma unroll
    for (int am = 0; am < 2; am++) {
#pragma unroll
        for (int a = 0; a < 4; a++) {
            int o0 = wc * 32 + 8 * a + 2 * t;
            int r0 = n0 + mo + 16 * am + g;
            int r1 = r0 + 8;
            if (o0 < DD) {
                if (r0 < NN) g_node[(size_t)r0 * DD + o0] = acc[am][a][0] + bbil_s[o0];
                if (r1 < NN) g_node[(size_t)r1 * DD + o0] = acc[am][a][2] + bbil_s[o0];
            }
            if (o0 + 1 < DD) {
                if (r0 < NN) g_node[(size_t)r0 * DD + o0 + 1] = acc[am][a][1] + bbil_s[o0 + 1];
                if (r1 < NN) g_node[(size_t)r1 * DD + o0 + 1] = acc[am][a][3] + bbil_s[o0 + 1];
            }
        }
    }
}

// ---------------------------------------------------------------------------
// Kernel 3 (fused GRN + head) — unchanged
// ---------------------------------------------------------------------------
__global__ __launch_bounds__(256) void grn_kernel(
    const float* __restrict__ nb, const float* __restrict__ sc,
    const float* __restrict__ Wg, const float* __restrict__ gb,
    const float* __restrict__ Wr, const float* __restrict__ br,
    float* __restrict__ out)
{
    __shared__ float Wg_s[2500];
    __shared__ float t_s[4][64];
    __shared__ float s_s[4][64];
    __shared__ float p_s[4][64];
    const int tid = threadIdx.x;
    const int n0 = blockIdx.x * 4;

    for (int idx = tid; idx < 2500; idx += 256) Wg_s[idx] = Wg[idx];
    {
        int v = tid >> 6, k = tid & 63;
        int n = n0 + v;
        s_s[v][k] = (n < NN) ? sc[(size_t)n * (KK + 1) + k] : 0.f;
    }
    __syncthreads();
    {
        int v = tid >> 6, d = tid & 63;
        int n = n0 + v;
        float acc = 0.f;
        if (n < NN && d < DD) {
            const float* basep = nb + (size_t)n * (KK * DD) + d;
#pragma unroll 9
            for (int k = 0; k < KK; k++) acc += s_s[v][k] * basep[k * DD];
            acc += s_s[v][KK] * g_node[(size_t)n * DD + d];
        }
        t_s[v][d] = acc;
    }
    __syncthreads();
    {
        int v = tid >> 6, o = tid & 63;
        float r = 0.f;
        if (o < DD) {
            float a = gb[o];
            const float* wrow = Wg_s + o * DD;
#pragma unroll
            for (int dd = 0; dd < DD; dd++) a += wrow[dd] * t_s[v][dd];
            float f = (a > 0.f) ? a : expm1f(a);
            r = f * Wr[o];
        }
        p_s[v][o] = r;
    }
    __syncthreads();
    if (tid < 4) {
        int n = n0 + tid;
        if (n < NN) {
            float sum = 0.f;
#pragma unroll
            for (int o = 0; o < 64; o++) sum += p_s[tid][o];
            out[n] = sum + br[0];
        }
    }
}

// ---------------------------------------------------------------------------
extern "C" void kernel_launch(void* const* d_in, const int* in_sizes, int n_in,
                              void* d_out, int out_size)
{
    const float* q    = (const float*)d_in[0];
    const float* ee   = (const float*)d_in[1];
    const float* nb   = (const float*)d_in[2];
    const float* sc   = (const float*)d_in[3];
    const float* Wp   = (const float*)d_in[4];
    const float* bp   = (const float*)d_in[5];
    const float* Wbil = (const float*)d_in[6];
    const float* bbil = (const float*)d_in[7];
    const float* Wg   = (const float*)d_in[8];
    const float* gb   = (const float*)d_in[9];
    const float* Wr   = (const float*)d_in[10];
    const float* br   = (const float*)d_in[11];
    float* out = (float*)d_out;

    dim3 blk(16, 16);
    const int nb64 = (NN + 63) / 64;
    prep_kernel<<<(50 * 2 * 16 * 32 + 255) / 256, 256>>>(Wbil);
    ent_kernel<<<nb64, blk>>>(ee, Wp, bp);
    bil_mma_kernel<<<(NN + 127) / 128, 256>>>(q, bbil);
    grn_kernel<<<(NN + 3) / 4, 256>>>(nb, sc, Wg, gb, Wr, br, out);
}

// round 7
// speedup vs baseline: 1.4620x; 1.2314x over previous
#include <cuda_runtime.h>
#include <cuda_bf16.h>
#include <math.h>
#include <stdint.h>

#define NN 20000
#define KK 63
#define DD 50
#define EE 300

// scratch (allocation-free rule: __device__ globals)
__device__ float g_ent[NN * DD];
__device__ float g_node[NN * DD];
// Wbil pre-split bf16 hi/lo in mma.sync fragment order:
// index ((i*2 + wc)*16 + s*4 + a)*32 + lane  -> uint2 {b0,b1},{b2,b3}
__device__ uint2 g_Bh[50 * 2 * 16 * 32];
__device__ uint2 g_Bl[50 * 2 * 16 * 32];

// ---------------------------------------------------------------------------
// mma.sync m16n8k16 row.col f32.bf16.bf16.f32 (sm_80-era PTX; compute_103-safe)
// ---------------------------------------------------------------------------
__device__ __forceinline__ void mma16816(float d[4], const uint32_t a[4],
                                         const uint2 b, const float c[4]) {
    asm volatile(
        "mma.sync.aligned.m16n8k16.row.col.f32.bf16.bf16.f32 "
        "{%0,%1,%2,%3}, {%4,%5,%6,%7}, {%8,%9}, {%10,%11,%12,%13};"
        : "=f"(d[0]), "=f"(d[1]), "=f"(d[2]), "=f"(d[3])
        : "r"(a[0]), "r"(a[1]), "r"(a[2]), "r"(a[3]),
          "r"(b.x), "r"(b.y),
          "f"(c[0]), "f"(c[1]), "f"(c[2]), "f"(c[3]));
}

__device__ __forceinline__ uint32_t pack_bf16x2(float lo, float hi) {
    __nv_bfloat162 h = __float22bfloat162_rn(make_float2(lo, hi));
    return *(uint32_t*)&h;
}

// ---------------------------------------------------------------------------
// Prep: split Wbil into bf16 hi/lo in B-fragment order (unchanged)
// ---------------------------------------------------------------------------
__global__ void prep_kernel(const float* __restrict__ Wbil) {
    int idx = blockIdx.x * 256 + threadIdx.x;
    if (idx >= 50 * 2 * 16 * 32) return;
    int lane = idx & 31;
    int frag = (idx >> 5) & 15;
    int wc   = (idx >> 9) & 1;
    int i    = idx >> 10;
    int s = frag >> 2, a = frag & 3;
    int g = lane >> 2, t = lane & 3;
    int o = wc * 32 + a * 8 + g;
    int j0 = s * 16 + 2 * t;

    float v[4];
    int js[4] = { j0, j0 + 1, j0 + 8, j0 + 9 };
#pragma unroll
    for (int e = 0; e < 4; e++) {
        int j = js[e];
        v[e] = (o < DD && j < DD) ? Wbil[o * 2500 + i * 50 + j] : 0.f;
    }
    uint2 hi, lo;
    {
        __nv_bfloat162 h = __float22bfloat162_rn(make_float2(v[0], v[1]));
        float l0 = v[0] - __bfloat162float(h.x);
        float l1 = v[1] - __bfloat162float(h.y);
        hi.x = *(uint32_t*)&h;
        lo.x = pack_bf16x2(l0, l1);
    }
    {
        __nv_bfloat162 h = __float22bfloat162_rn(make_float2(v[2], v[3]));
        float l0 = v[2] - __bfloat162float(h.x);
        float l1 = v[3] - __bfloat162float(h.y);
        hi.y = *(uint32_t*)&h;
        lo.y = pack_bf16x2(l0, l1);
    }
    g_Bh[idx] = hi;
    g_Bl[idx] = lo;
}

// ---------------------------------------------------------------------------
// Kernel 1: ent = entity_emb @ Wp.T + bp  (fp32 tiled GEMM, unchanged)
// ---------------------------------------------------------------------------
__global__ __launch_bounds__(256) void ent_kernel(
    const float* __restrict__ eemb, const float* __restrict__ Wp,
    const float* __restrict__ bp)
{
    __shared__ float e_s[64][52];
    __shared__ float w_s[50][52];
    const int tx = threadIdx.x, ty = threadIdx.y;
    const int tid = ty * 16 + tx;
    const int n0 = blockIdx.x * 64;

    int  oc[4];
    bool ov[4];
#pragma unroll
    for (int cc = 0; cc < 4; cc++) {
        int o = cc * 13 + tx;
        ov[cc] = (tx < 13) && (o < DD);
        oc[cc] = ov[cc] ? o : 0;
    }
    float acc[4][4] = {};
    for (int cb = 0; cb < EE; cb += 50) {
        __syncthreads();
        for (int idx = tid; idx < 64 * 52; idx += 256) {
            int r = idx / 52, c = idx - r * 52;
            int n = n0 + r;
            e_s[r][c] = (c < 50 && n < NN) ? eemb[(size_t)n * EE + cb + c] : 0.f;
        }
        for (int idx = tid; idx < 50 * 52; idx += 256) {
            int r = idx / 52, c = idx - r * 52;
            w_s[r][c] = (c < 50) ? Wp[r * EE + cb + c] : 0.f;
        }
        __syncthreads();
#pragma unroll
        for (int j = 0; j < 52; j += 4) {
            float4 ev[4], bv[4];
#pragma unroll
            for (int rr = 0; rr < 4; rr++) ev[rr] = *(const float4*)&e_s[ty * 4 + rr][j];
#pragma unroll
            for (int cc = 0; cc < 4; cc++) bv[cc] = *(const float4*)&w_s[oc[cc]][j];
#pragma unroll
            for (int rr = 0; rr < 4; rr++)
#pragma unroll
                for (int cc = 0; cc < 4; cc++)
                    acc[rr][cc] += ev[rr].x * bv[cc].x + ev[rr].y * bv[cc].y
                                 + ev[rr].z * bv[cc].z + ev[rr].w * bv[cc].w;
        }
    }
#pragma unroll
    for (int rr = 0; rr < 4; rr++) {
        int n = n0 + ty * 4 + rr;
        if (n < NN) {
#pragma unroll
            for (int cc = 0; cc < 4; cc++)
                if (ov[cc]) g_ent[(size_t)n * DD + oc[cc]] = acc[rr][cc] + bp[oc[cc]];
        }
    }
}

// ---------------------------------------------------------------------------
// Kernel 2 (HMMA): node[n,o] = sum_i q[n,i] * (ent @ Wbil[:,i,:].T)[n,o] + bbil
// 64 nodes/CTA, 4 warps (2m x 2n), warp tile 32(m) x 32(n).
// launch_bounds(128,3): 313 CTAs fit one wave at occ 3 -> 12 warps/SM.
// ---------------------------------------------------------------------------
extern "C" __global__ void __launch_bounds__(128, 3)
bil_mma_kernel(const float* __restrict__ q, const float* __restrict__ bbil)
{
    __shared__ float sm[64 * 64];        // phase 1: ent[64][64]; phase 2: q_t[50][64]
    __shared__ float bbil_s[64];

    const int tid = threadIdx.x;
    const int lane = tid & 31, wid = tid >> 5;
    const int n0 = blockIdx.x * 64;
    const int g = lane >> 2, t = lane & 3;
    const int mo = (wid >> 1) * 32;      // warp m offset (0/32)
    const int wc = wid & 1;              // warp n column (0/1)

    // ---- phase 1: stage ent (padded to 64 cols with zeros) ----
    for (int idx = tid; idx < 64 * 50; idx += 128) {
        int r = idx / 50, c = idx - r * 50;
        int n = n0 + r;
        sm[r * 64 + c] = (n < NN) ? g_ent[(size_t)n * DD + c] : 0.f;
    }
    for (int idx = tid; idx < 64 * 14; idx += 128) {
        int r = idx / 14, c = idx - r * 14;
        sm[r * 64 + 50 + c] = 0.f;
    }
    if (tid < 64) bbil_s[tid] = (tid < DD) ? bbil[tid] : 0.f;
    __syncthreads();

    // gather loop-invariant A fragments (hi/lo split once)
    uint32_t eh[2][4][4], el[2][4][4];
#pragma unroll
    for (int am = 0; am < 2; am++) {
#pragma unroll
        for (int s = 0; s < 4; s++) {
            int r0 = mo + 16 * am + g, r1 = r0 + 8;
            int c0 = 16 * s + 2 * t;
            float a0 = sm[r0 * 64 + c0],     a1 = sm[r0 * 64 + c0 + 1];
            float a2 = sm[r1 * 64 + c0],     a3 = sm[r1 * 64 + c0 + 1];
            float a4 = sm[r0 * 64 + c0 + 8], a5 = sm[r0 * 64 + c0 + 9];
            float a6 = sm[r1 * 64 + c0 + 8], a7 = sm[r1 * 64 + c0 + 9];
            float v[8] = { a0, a1, a2, a3, a4, a5, a6, a7 };
#pragma unroll
            for (int p = 0; p < 4; p++) {
                __nv_bfloat162 h = __float22bfloat162_rn(make_float2(v[2 * p], v[2 * p + 1]));
                float l0 = v[2 * p]     - __bfloat162float(h.x);
                float l1 = v[2 * p + 1] - __bfloat162float(h.y);
                eh[am][s][p] = *(uint32_t*)&h;
                el[am][s][p] = pack_bf16x2(l0, l1);
            }
        }
    }
    __syncthreads();

    // ---- phase 2: reuse smem for q transposed [50][64] ----
    for (int idx = tid; idx < 64 * 50; idx += 128) {
        int r = idx / 50, c = idx - r * 50;
        int n = n0 + r;
        sm[c * 64 + r] = (n < NN) ? q[(size_t)n * DD + c] : 0.f;
    }
    __syncthreads();

    float acc[2][4][4] = {};

    for (int i = 0; i < 50; i++) {
        const float* qrow = sm + i * 64 + mo;
        float qv[4] = { qrow[g], qrow[g + 8], qrow[g + 16], qrow[g + 24] };

        float d[2][4][4];
#pragma unroll
        for (int am = 0; am < 2; am++)
#pragma unroll
            for (int a = 0; a < 4; a++)
#pragma unroll
                for (int e = 0; e < 4; e++) d[am][a][e] = 0.f;

        const int base = ((i * 2 + wc) * 16) * 32 + lane;
#pragma unroll
        for (int s = 0; s < 4; s++) {
            uint2 bh[4], bl[4];
#pragma unroll
            for (int a = 0; a < 4; a++) {
                bh[a] = g_Bh[base + (s * 4 + a) * 32];
                bl[a] = g_Bl[base + (s * 4 + a) * 32];
            }
#pragma unroll
            for (int a = 0; a < 4; a++) {
#pragma unroll
                for (int am = 0; am < 2; am++) {
                    mma16816(d[am][a], eh[am][s], bh[a], d[am][a]);
                    mma16816(d[am][a], el[am][s], bh[a], d[am][a]);
                    mma16816(d[am][a], eh[am][s], bl[a], d[am][a]);
                }
            }
        }
#pragma unroll
        for (int am = 0; am < 2; am++) {
            float q0 = qv[2 * am], q1 = qv[2 * am + 1];
#pragma unroll
            for (int a = 0; a < 4; a++) {
                acc[am][a][0] += q0 * d[am][a][0];
                acc[am][a][1] += q0 * d[am][a][1];
                acc[am][a][2] += q1 * d[am][a][2];
                acc[am][a][3] += q1 * d[am][a][3];
            }
        }
    }

    // epilogue
#pragma unroll
    for (int am = 0; am < 2; am++) {
#pragma unroll
        for (int a = 0; a < 4; a++) {
            int o0 = wc * 32 + 8 * a + 2 * t;
            int r0 = n0 + mo + 16 * am + g;
            int r1 = r0 + 8;
            if (o0 < DD) {
                if (r0 < NN) g_node[(size_t)r0 * DD + o0] = acc[am][a][0] + bbil_s[o0];
                if (r1 < NN) g_node[(size_t)r1 * DD + o0] = acc[am][a][2] + bbil_s[o0];
            }
            if (o0 + 1 < DD) {
                if (r0 < NN) g_node[(size_t)r0 * DD + o0 + 1] = acc[am][a][1] + bbil_s[o0 + 1];
                if (r1 < NN) g_node[(size_t)r1 * DD + o0 + 1] = acc[am][a][3] + bbil_s[o0 + 1];
            }
        }
    }
}

// ---------------------------------------------------------------------------
// Kernel 3 (GRN + head): warp-per-node, float2 neighbor loads, shfl head.
// 8 nodes / 256-thread block; 2500 blocks.
// ---------------------------------------------------------------------------
__global__ __launch_bounds__(256) void grn_kernel(
    const float* __restrict__ nb, const float* __restrict__ sc,
    const float* __restrict__ Wg, const float* __restrict__ gb,
    const float* __restrict__ Wr, const float* __restrict__ br,
    float* __restrict__ out)
{
    __shared__ float Wg_s[50 * 51];      // stride 51: conflict-free column walks
    __shared__ float t_s[8][52];
    __shared__ float s_s[8][64];
    const int tid = threadIdx.x;
    const int lane = tid & 31, v = tid >> 5;    // warp v handles node n0+v
    const int n0 = blockIdx.x * 8;
    const int n = n0 + v;
    const bool ok = (n < NN);

    for (int idx = tid; idx < 2500; idx += 256) {
        int o = idx / 50, dd = idx - o * 50;
        Wg_s[o * 51 + dd] = Wg[idx];
    }
    {
        float s0 = ok ? sc[(size_t)n * (KK + 1) + lane] : 0.f;
        float s1 = ok ? sc[(size_t)n * (KK + 1) + 32 + lane] : 0.f;
        s_s[v][lane] = s0;
        s_s[v][32 + lane] = s1;
    }
    __syncthreads();

    // phase 1: weighted neighbor sum; lanes 0..24 own float2 at d = 2*lane
    if (lane < 25) {
        float2 acc = make_float2(0.f, 0.f);
        if (ok) {
            const float* base = nb + (size_t)n * (KK * DD) + 2 * lane;
#pragma unroll 9
            for (int k = 0; k < KK; k++) {
                float2 vv = *(const float2*)(base + k * DD);
                float sk = s_s[v][k];
                acc.x += sk * vv.x;
                acc.y += sk * vv.y;
            }
            float2 nd = *(const float2*)(g_node + (size_t)n * DD + 2 * lane);
            float s63 = s_s[v][KK];
            acc.x += s63 * nd.x;
            acc.y += s63 * nd.y;
        }
        t_s[v][2 * lane] = acc.x;
        t_s[v][2 * lane + 1] = acc.y;
    }
    __syncwarp();

    // phase 2: Wg matvec + bias + ELU + Wr scale; 2 o's per lane
    float r = 0.f;
#pragma unroll
    for (int h = 0; h < 2; h++) {
        int o = lane + 32 * h;
        if (o < DD) {
            float a = gb[o];
            const float* wrow = Wg_s + o * 51;
#pragma unroll
            for (int dd = 0; dd < DD; dd++) a += wrow[dd] * t_s[v][dd];
            float f = (a > 0.f) ? a : expm1f(a);
            r += f * Wr[o];
        }
    }
#pragma unroll
    for (int off = 16; off; off >>= 1) r += __shfl_xor_sync(0xffffffffu, r, off);
    if (lane == 0 && ok) out[n] = r + br[0];
}

// ---------------------------------------------------------------------------
extern "C" void kernel_launch(void* const* d_in, const int* in_sizes, int n_in,
                              void* d_out, int out_size)
{
    const float* q    = (const float*)d_in[0];
    const float* ee   = (const float*)d_in[1];
    const float* nb   = (const float*)d_in[2];
    const float* sc   = (const float*)d_in[3];
    const float* Wp   = (const float*)d_in[4];
    const float* bp   = (const float*)d_in[5];
    const float* Wbil = (const float*)d_in[6];
    const float* bbil = (const float*)d_in[7];
    const float* Wg   = (const float*)d_in[8];
    const float* gb   = (const float*)d_in[9];
    const float* Wr   = (const float*)d_in[10];
    const float* br   = (const float*)d_in[11];
    float* out = (float*)d_out;

    dim3 blk(16, 16);
    const int nb64 = (NN + 63) / 64;
    prep_kernel<<<(50 * 2 * 16 * 32 + 255) / 256, 256>>>(Wbil);
    ent_kernel<<<nb64, blk>>>(ee, Wp, bp);
    bil_mma_kernel<<<(NN + 63) / 64, 128>>>(q, bbil);
    grn_kernel<<<(NN + 7) / 8, 256>>>(nb, sc, Wg, gb, Wr, br, out);
}